// round 15
// baseline (speedup 1.0000x reference)
#include <cuda_runtime.h>
#include <cuda_fp16.h>
#include <math.h>
#include <stdint.h>

#define DIMD  1024
#define ADIMD 256
#define HIDD  4096
#define NTOK  4096
#define NB    4
#define MROWS (NB * NTOK)        // 16384
#define DEPTH 4
#define SCALE_A 0.25f

// ---------------- scratch (device globals) ----------------
__device__ __half g_h   [(size_t)MROWS * DIMD];
__device__ __half g_qk  [(size_t)MROWS * 512];      // q = cols [0,256), k = [256,512)
__device__ __half g_att [(size_t)MROWS * ADIMD];
__device__ __half g_hid [(size_t)MROWS * HIDD];
__device__ float  g_a   [MROWS];
__device__ float  g_G   [NB * ADIMD];
__device__ float  g_Gp  [256 * ADIMD];
__device__ float  g_bqk [DEPTH * 512];
__device__ __half g_Wqkt[(size_t)DEPTH * 512 * DIMD];   // [Wq|Wk] transposed
__device__ __half g_Wpt [(size_t)DEPTH * ADIMD * ADIMD];
__device__ __half g_Wft [(size_t)DEPTH * DIMD * ADIMD];
__device__ __half g_W1t [(size_t)DEPTH * HIDD * DIMD];
__device__ __half g_W2t [(size_t)DEPTH * DIMD * HIDD];

// ---------------- helpers ----------------
__device__ __forceinline__ float warpSum(float v) {
#pragma unroll
    for (int o = 16; o > 0; o >>= 1) v += __shfl_xor_sync(0xFFFFFFFFu, v, o);
    return v;
}
__device__ __forceinline__ uint32_t smem_u32(const void* p) {
    uint32_t a;
    asm("{ .reg .u64 t; cvta.to.shared.u64 t, %1; cvt.u32.u64 %0, t; }" : "=r"(a) : "l"(p));
    return a;
}
__device__ __forceinline__ void cp_async16(uint32_t saddr, const void* g) {
    asm volatile("cp.async.cg.shared.global [%0], [%1], 16;" :: "r"(saddr), "l"(g));
}
__device__ __forceinline__ void cp_commit() { asm volatile("cp.async.commit_group;"); }
template <int N> __device__ __forceinline__ void cp_wait() {
    asm volatile("cp.async.wait_group %0;" :: "n"(N));
}
__device__ __forceinline__ void ldsm4(uint32_t& r0, uint32_t& r1, uint32_t& r2, uint32_t& r3,
                                      uint32_t addr) {
    asm volatile("ldmatrix.sync.aligned.m8n8.x4.shared.b16 {%0,%1,%2,%3}, [%4];"
                 : "=r"(r0), "=r"(r1), "=r"(r2), "=r"(r3) : "r"(addr));
}
__device__ __forceinline__ void mma_f16(float& c0, float& c1, float& c2, float& c3,
                                        uint32_t a0, uint32_t a1, uint32_t a2, uint32_t a3,
                                        uint32_t b0, uint32_t b1) {
    asm volatile(
        "mma.sync.aligned.m16n8k16.row.col.f32.f16.f16.f32 "
        "{%0,%1,%2,%3}, {%4,%5,%6,%7}, {%8,%9}, {%0,%1,%2,%3};"
        : "+f"(c0), "+f"(c1), "+f"(c2), "+f"(c3)
        : "r"(a0), "r"(a1), "r"(a2), "r"(a3), "r"(b0), "r"(b1));
}

// == fp16 GEMM: CTA 128x128, 4 warps (2x2) of 64x64, K processed in 64-pairs =
#define A_BYTES     10240                 // 128 rows x 40 halfs (80B)
#define STAGE_BYTES 20480                 // A + B (32-deep K chunk)
#define NSTAGE      4                     // 2 pairs of 2 stages
#define SMEM_HGEMM  (NSTAGE * STAGE_BYTES)  // 81920

// EPI: 0 = half(AB+bias) | 1 = Cf32 += AB+bias | 2 = half(gelu(AB+bias))
//      3 = half(AB+bias+Dhalf) | 4 = Cf32 = AB+bias+Dfloat
template <int EPI>
__global__ __launch_bounds__(128, 2)
void hgemm(int N, int K, int lda, int ldd,
           const __half* __restrict__ A,
           const __half* __restrict__ Bt,
           const float* __restrict__ bias,
           const void* __restrict__ Dadd,
           void* __restrict__ Cv) {
    extern __shared__ char smraw[];
    const uint32_t sbase = smem_u32(smraw);

    const int bx = blockIdx.x, by = blockIdx.y;
    const int tid = threadIdx.x;
    const int lane = tid & 31;
    const int warp = tid >> 5;           // 0..3
    const int warpM = warp & 1;          // 2 warps over M (64 rows each)
    const int warpN = warp >> 1;         // 2 warps over N (64 cols each)
    const int tg  = lane & 3;

    const __half* Ab = A  + (size_t)by * 128 * lda;
    const __half* Bb = Bt + (size_t)bx * 128 * K;

    const uint32_t a_lane = (uint32_t)((warpM * 64 + (lane & 15)) * 80 + (lane >> 4) * 16);
    const uint32_t b_lane = (uint32_t)(A_BYTES +
        (warpN * 64 + (lane & 7) + 8 * (lane >> 4)) * 80 + ((lane >> 3) & 1) * 16);

    float acc[4][8][4];
#pragma unroll
    for (int mi = 0; mi < 4; mi++)
#pragma unroll
        for (int ni = 0; ni < 8; ni++)
#pragma unroll
            for (int r = 0; r < 4; r++) acc[mi][ni][r] = 0.f;

    // double-buffered fragments
    uint32_t aF[2][4][4];     // [buf][mi][reg]
    uint32_t bF[2][8][2];     // [buf][ni][reg]

    const int P = K / 64;     // pairs of 32-deep chunks

    // one 32-deep chunk: A 512 16B-chunks + B 512 — 4+4 per thread (128 thr)
#define LOAD_HALF(t_, s_) do {                                                    \
        uint32_t _sa = sbase + (s_) * STAGE_BYTES;                                \
        uint32_t _sb = _sa + A_BYTES;                                             \
        const __half* _ga = Ab + (size_t)(t_) * 32;                              \
        const __half* _gb = Bb + (size_t)(t_) * 32;                              \
        _Pragma("unroll")                                                         \
        for (int _i = 0; _i < 4; _i++) {                                          \
            int _id = tid + _i * 128;                                             \
            int _r = _id >> 2, _c = _id & 3;                                      \
            cp_async16(_sa + _r * 80 + _c * 16, _ga + (size_t)_r * lda + _c * 8); \
            cp_async16(_sb + _r * 80 + _c * 16, _gb + (size_t)_r * K + _c * 8);   \
        }                                                                         \
    } while (0)

#define LOAD_PAIR(p_, s_) do {                                                    \
        LOAD_HALF(2 * (p_),     (s_));                                            \
        LOAD_HALF(2 * (p_) + 1, (s_) + 1);                                        \
        cp_commit();                                                              \
    } while (0)

#define LDSM_FRAGS(bufi, st_, ks_) do {                                           \
        uint32_t _a0 = (st_) + a_lane + (ks_) * 32;                               \
        _Pragma("unroll")                                                         \
        for (int _mi = 0; _mi < 4; _mi++)                                         \
            ldsm4(aF[bufi][_mi][0], aF[bufi][_mi][1],                             \
                  aF[bufi][_mi][2], aF[bufi][_mi][3], _a0 + _mi * 1280);          \
        uint32_t _b0 = (st_) + b_lane + (ks_) * 32;                               \
        _Pragma("unroll")                                                         \
        for (int _p = 0; _p < 4; _p++)                                            \
            ldsm4(bF[bufi][2*_p][0], bF[bufi][2*_p][1],                           \
                  bF[bufi][2*_p+1][0], bF[bufi][2*_p+1][1], _b0 + _p * 1280);     \
    } while (0)

#define DO_MMA(bufi) do {                                                         \
        _Pragma("unroll")                                                         \
        for (int mi = 0; mi < 4; mi++)                                            \
            _Pragma("unroll")                                                     \
            for (int ni = 0; ni < 8; ni++)                                        \
                mma_f16(acc[mi][ni][0], acc[mi][ni][1],                           \
                        acc[mi][ni][2], acc[mi][ni][3],                           \
                        aF[bufi][mi][0], aF[bufi][mi][1],                         \
                        aF[bufi][mi][2], aF[bufi][mi][3],                         \
                        bF[bufi][ni][0], bF[bufi][ni][1]);                        \
    } while (0)

    // prologue: pairs 0 and 1 in flight (K >= 256 so P >= 4 always)
    LOAD_PAIR(0, 0);
    LOAD_PAIR(1, 2);
    cp_wait<1>();
    __syncthreads();
    LDSM_FRAGS(0, sbase, 0);        // pair0 chunk0 ks0

    for (int p = 0; p < P; p++) {
        const uint32_t st0 = sbase + ((p & 1) * 2) * STAGE_BYTES;
        const uint32_t st1 = st0 + STAGE_BYTES;
        LDSM_FRAGS(1, st0, 1);  DO_MMA(0);
        LDSM_FRAGS(0, st1, 0);  DO_MMA(1);
        LDSM_FRAGS(1, st1, 1);  DO_MMA(0);
        if (p + 1 < P) {
            cp_wait<0>();               // pair p+1 resident (only group in flight)
            __syncthreads();            // all reads of pair p done -> slots reusable
            if (p + 2 < P) LOAD_PAIR(p + 2, (p & 1) * 2);
            LDSM_FRAGS(0, sbase + (((p + 1) & 1) * 2) * STAGE_BYTES, 0);
        }
        DO_MMA(1);
    }

    // epilogue
    const int grp8 = lane >> 2;
#pragma unroll
    for (int mi = 0; mi < 4; mi++) {
#pragma unroll
        for (int ni = 0; ni < 8; ni++) {
            int col = bx * 128 + warpN * 64 + ni * 8 + 2 * tg;
            int row0 = by * 128 + warpM * 64 + mi * 16 + grp8;
            float bv0 = bias[col], bv1 = bias[col + 1];
#pragma unroll
            for (int hh = 0; hh < 2; hh++) {
                int row = row0 + hh * 8;
                float v0 = acc[mi][ni][hh * 2 + 0] + bv0;
                float v1 = acc[mi][ni][hh * 2 + 1] + bv1;
                if (EPI == 1) {
                    float* Cp = (float*)Cv + (size_t)row * N + col;
                    float2 old = *(const float2*)Cp;
                    *(float2*)Cp = make_float2(v0 + old.x, v1 + old.y);
                } else if (EPI == 4) {
                    const float2 dv = *(const float2*)((const float*)Dadd +
                                                       (size_t)row * ldd + col);
                    float* Cp = (float*)Cv + (size_t)row * N + col;
                    *(float2*)Cp = make_float2(v0 + dv.x, v1 + dv.y);
                } else {
                    __half* Cp = (__half*)Cv + (size_t)row * N + col;
                    if (EPI == 2) {
                        v0 = 0.5f * v0 * (1.0f + erff(v0 * 0.70710678118654752f));
                        v1 = 0.5f * v1 * (1.0f + erff(v1 * 0.70710678118654752f));
                    }
                    if (EPI == 3) {
                        float2 dv = __half22float2(
                            *(const __half2*)((const __half*)Dadd +
                                              (size_t)row * ldd + col));
                        v0 += dv.x; v1 += dv.y;
                    }
                    *(__half2*)Cp = __floats2half2_rn(v0, v1);
                }
            }
        }
    }
}

// -------- single-launch transpose of ALL weights ---------------------------
#define TRANS_BLOCKS 36096
__global__ void transpose_all(const float* __restrict__ Wq, const float* __restrict__ Wk,
                              const float* __restrict__ Wp, const float* __restrict__ Wf,
                              const float* __restrict__ W1, const float* __restrict__ W2,
                              __half* __restrict__ Wqkt,
                              __half* __restrict__ Wpt, __half* __restrict__ Wft,
                              __half* __restrict__ W1t, __half* __restrict__ W2t) {
    int id = blockIdx.x;
    const float* W; __half* Wt; int K, N, base, orow;
    size_t ostride;
    if      (id < 1024)  { W = Wq; Wt = Wqkt; K = DIMD;  N = ADIMD; base = 0;
                           ostride = (size_t)512 * DIMD; orow = 0; }
    else if (id < 2048)  { W = Wk; Wt = Wqkt; K = DIMD;  N = ADIMD; base = 1024;
                           ostride = (size_t)512 * DIMD; orow = 256; }
    else if (id < 2304)  { W = Wp; Wt = Wpt;  K = ADIMD; N = ADIMD; base = 2048;
                           ostride = (size_t)K * N; orow = 0; }
    else if (id < 3328)  { W = Wf; Wt = Wft;  K = ADIMD; N = DIMD;  base = 2304;
                           ostride = (size_t)K * N; orow = 0; }
    else if (id < 19712) { W = W1; Wt = W1t;  K = DIMD;  N = HIDD;  base = 3328;
                           ostride = (size_t)K * N; orow = 0; }
    else                 { W = W2; Wt = W2t;  K = HIDD;  N = DIMD;  base = 19712;
                           ostride = (size_t)K * N; orow = 0; }
    int lid = id - base;
    int ntN = N >> 5;
    int tpl = (K >> 5) * ntN;
    int layer = lid / tpl;
    int rem   = lid % tpl;
    int n0 = (rem % ntN) * 32, k0 = (rem / ntN) * 32;
    size_t ioff = (size_t)layer * K * N;
    size_t ooff = (size_t)layer * ostride;

    __shared__ float t[32][33];
    int tx = threadIdx.x, ty = threadIdx.y;   // 32 x 8
#pragma unroll
    for (int i = 0; i < 4; i++)
        t[ty + 8 * i][tx] = W[ioff + (size_t)(k0 + ty + 8 * i) * N + n0 + tx];
    __syncthreads();
#pragma unroll
    for (int i = 0; i < 4; i++)
        Wt[ooff + (size_t)(orow + n0 + ty + 8 * i) * K + k0 + tx] =
            __float2half(t[tx][ty + 8 * i]);
}

// -------- pack [bq|bk] per layer -------------------------------------------
__global__ void pack_bias(const float* __restrict__ bq, const float* __restrict__ bk,
                          float* __restrict__ bqk) {
    int l = blockIdx.x, j = threadIdx.x;        // 512 threads
    bqk[l * 512 + j] = (j < 256) ? bq[l * 256 + j] : bk[l * 256 + j - 256];
}

// ---------------- LayerNorm: one warp per row ------------------------------
__global__ void ln_kernel(const float* __restrict__ x,
                          const float* __restrict__ g,
                          const float* __restrict__ b,
                          __half* __restrict__ out) {
    int row  = blockIdx.x * 8 + (threadIdx.x >> 5);
    int lane = threadIdx.x & 31;
    const float4* xr = (const float4*)(x + (size_t)row * DIMD);
    float4 v[8];
    float s = 0.f, s2 = 0.f;
#pragma unroll
    for (int j = 0; j < 8; j++) {
        v[j] = xr[lane + j * 32];
        s  += v[j].x + v[j].y + v[j].z + v[j].w;
        s2 += v[j].x*v[j].x + v[j].y*v[j].y + v[j].z*v[j].z + v[j].w*v[j].w;
    }
    s = warpSum(s); s2 = warpSum(s2);
    float mu  = s * (1.f / DIMD);
    float var = s2 * (1.f / DIMD) - mu * mu;
    float rs  = rsqrtf(var + 1e-6f);
    const float4* g4 = (const float4*)g;
    const float4* b4 = (const float4*)b;
    uint2* o = (uint2*)(out + (size_t)row * DIMD);
#pragma unroll
    for (int j = 0; j < 8; j++) {
        int c4 = lane + j * 32;
        float4 gg = g4[c4], bb = b4[c4];
        float o0 = (v[j].x - mu) * rs * gg.x + bb.x;
        float o1 = (v[j].y - mu) * rs * gg.y + bb.y;
        float o2 = (v[j].z - mu) * rs * gg.z + bb.z;
        float o3 = (v[j].w - mu) * rs * gg.w + bb.w;
        __half2 h0 = __floats2half2_rn(o0, o1);
        __half2 h1 = __floats2half2_rn(o2, o3);
        uint2 u;
        u.x = *(uint32_t*)&h0; u.y = *(uint32_t*)&h1;
        o[c4] = u;
    }
}

// ---- fused q pipeline: l2norm rows + a=SCALE*dot(qn,wg) + Gp partial -----
__global__ void rnq_gsum_kernel(__half* __restrict__ qk,
                                const float* __restrict__ wg,
                                float* __restrict__ a_out,
                                float* __restrict__ Gp) {
    __shared__ float a_sh[64];
    const int warp = threadIdx.x >> 5, lane = threadIdx.x & 31;
    const int row0 = blockIdx.x * 64;
    const float4* w4 = (const float4*)wg;
    const float4 w0 = w4[lane * 2], w1 = w4[lane * 2 + 1];

#pragma unroll 2
    for (int i = 0; i < 8; i++) {
        int r = warp * 8 + i;
        int row = row0 + r;
        float4* rp = (float4*)(qk + (size_t)row * 512);
        float4 v = rp[lane];
        __half2* h2 = (__half2*)&v;
        float2 f[4];
        float s = 0.f;
#pragma unroll
        for (int j = 0; j < 4; j++) {
            f[j] = __half22float2(h2[j]);
            s += f[j].x * f[j].x + f[j].y * f[j].y;
        }
        s = warpSum(s);
        float inv = 1.0f / fmaxf(sqrtf(s), 1e-12f);
#pragma unroll
        for (int j = 0; j < 4; j++) {
            f[j].x *= inv; f[j].y *= inv;
            h2[j] = __floats2half2_rn(f[j].x, f[j].y);
        }
        float d = f[0].x * w0.x + f[0].y * w0.y + f[1].x * w0.z + f[1].y * w0.w
                + f[2].x * w1.x + f[2].y * w1.y + f[3].x * w1.z + f[3].y * w1.w;
        d = warpSum(d);
        rp[lane] = v;
        if (lane == 0) {
            float av = d * SCALE_A;
            a_sh[r] = av;
            a_out[row] = av;
        }
    }
    __syncthreads();

    int c = threadIdx.x;
    const __half* qb = qk + (size_t)row0 * 512;
    float s = 0.f;
#pragma unroll 4
    for (int n = 0; n < 64; n++)
        s += a_sh[n] * __half2float(qb[(size_t)n * 512 + c]);
    Gp[(size_t)blockIdx.x * ADIMD + c] = s;
}

// ---- gsum2 with fused a-norm ----------------------------------------------
__global__ void gsum2_kernel(const float* __restrict__ Gp,
                             const float* __restrict__ a,
                             float* __restrict__ G) {
    int b = blockIdx.x;
    int c = threadIdx.x;
    float s = 0.f;
    for (int n = c; n < NTOK; n += 256) {
        float v = a[b * NTOK + n];
        s += v * v;
    }
    __shared__ float sh[8];
    s = warpSum(s);
    int w = c >> 5, l = c & 31;
    if (l == 0) sh[w] = s;
    __syncthreads();
    __shared__ float rn_sh;
    if (w == 0) {
        float v = (l < 8) ? sh[l] : 0.f;
        v = warpSum(v);
        if (l == 0) rn_sh = 1.0f / fmaxf(sqrtf(v), 1e-12f);
    }
    __syncthreads();
    float g = 0.f;
#pragma unroll
    for (int ch = 0; ch < 64; ch++)
        g += Gp[((size_t)b * 64 + ch) * ADIMD + c];
    G[b * ADIMD + c] = g * rn_sh;
}

// ---- k: l2norm + G scaling fused ------------------------------------------
__global__ void rnk_scale_kernel(__half* __restrict__ qk, const float* __restrict__ G) {
    int row  = blockIdx.x * 8 + (threadIdx.x >> 5);
    int lane = threadIdx.x & 31;
    int b = row >> 12;
    float4* r = (float4*)(qk + (size_t)row * 512 + 256);
    float4 v = r[lane];
    __half2* h2 = (__half2*)&v;
    float2 f[4];
    float s = 0.f;
#pragma unroll
    for (int i = 0; i < 4; i++) {
        f[i] = __half22float2(h2[i]);
        s += f[i].x * f[i].x + f[i].y * f[i].y;
    }
    s = warpSum(s);
    float inv = 1.0f / fmaxf(sqrtf(s), 1e-12f);
    const float4* G4 = (const float4*)(G + b * ADIMD);
    float4 g0 = G4[lane * 2], g1 = G4[lane * 2 + 1];
    h2[0] = __floats2half2_rn(f[0].x * inv * g0.x, f[0].y * inv * g0.y);
    h2[1] = __floats2half2_rn(f[1].x * inv * g0.z, f[1].y * inv * g0.w);
    h2[2] = __floats2half2_rn(f[2].x * inv * g1.x, f[2].y * inv * g1.y);
    h2[3] = __floats2half2_rn(f[3].x * inv * g1.z, f[3].y * inv * g1.w);
    r[lane] = v;
}

// ---------------- host orchestration --------------------------------------
extern "C" void kernel_launch(void* const* d_in, const int* in_sizes, int n_in,
                              void* d_out, int out_size) {
    const float* x_in  = (const float*)d_in[0];
    const float* ln1_g = (const float*)d_in[1];
    const float* ln1_b = (const float*)d_in[2];
    const float* Wq    = (const float*)d_in[3];
    const float* bq    = (const float*)d_in[4];
    const float* Wk    = (const float*)d_in[5];
    const float* bk    = (const float*)d_in[6];
    const float* w_g   = (const float*)d_in[7];
    const float* Wp    = (const float*)d_in[8];
    const float* bp    = (const float*)d_in[9];
    const float* Wf    = (const float*)d_in[10];
    const float* bf    = (const float*)d_in[11];
    const float* ln2_g = (const float*)d_in[12];
    const float* ln2_b = (const float*)d_in[13];
    const float* W1    = (const float*)d_in[14];
    const float* b1    = (const float*)d_in[15];
    const float* W2    = (const float*)d_in[16];
    const float* b2    = (const float*)d_in[17];

    float* x = (float*)d_out;

    void* p;
    cudaGetSymbolAddress(&p, g_h);    __half* h    = (__half*)p;
    cudaGetSymbolAddress(&p, g_qk);   __half* qk   = (__half*)p;
    cudaGetSymbolAddress(&p, g_att);  __half* att  = (__half*)p;
    cudaGetSymbolAddress(&p, g_hid);  __half* hid  = (__half*)p;
    cudaGetSymbolAddress(&p, g_a);    float* a     = (float*)p;
    cudaGetSymbolAddress(&p, g_G);    float* G     = (float*)p;
    cudaGetSymbolAddress(&p, g_Gp);   float* Gp    = (float*)p;
    cudaGetSymbolAddress(&p, g_bqk);  float* bqk   = (float*)p;
    cudaGetSymbolAddress(&p, g_Wqkt); __half* Wqkt = (__half*)p;
    cudaGetSymbolAddress(&p, g_Wpt);  __half* Wpt  = (__half*)p;
    cudaGetSymbolAddress(&p, g_Wft);  __half* Wft  = (__half*)p;
    cudaGetSymbolAddress(&p, g_W1t);  __half* W1t  = (__half*)p;
    cudaGetSymbolAddress(&p, g_W2t);  __half* W2t  = (__half*)p;

    cudaFuncSetAttribute(hgemm<0>, cudaFuncAttributeMaxDynamicSharedMemorySize, SMEM_HGEMM);
    cudaFuncSetAttribute(hgemm<1>, cudaFuncAttributeMaxDynamicSharedMemorySize, SMEM_HGEMM);
    cudaFuncSetAttribute(hgemm<2>, cudaFuncAttributeMaxDynamicSharedMemorySize, SMEM_HGEMM);
    cudaFuncSetAttribute(hgemm<3>, cudaFuncAttributeMaxDynamicSharedMemorySize, SMEM_HGEMM);
    cudaFuncSetAttribute(hgemm<4>, cudaFuncAttributeMaxDynamicSharedMemorySize, SMEM_HGEMM);

    transpose_all<<<TRANS_BLOCKS, dim3(32, 8)>>>(Wq, Wk, Wp, Wf, W1, W2,
                                                 Wqkt, Wpt, Wft, W1t, W2t);
    pack_bias<<<DEPTH, 512>>>(bq, bk, bqk);

    const dim3 gQK2(512  / 128, MROWS / 128);   // (4, 128)
    const dim3 gP  (ADIMD / 128, MROWS / 128);  // (2, 128)
    const dim3 gDIM(DIMD  / 128, MROWS / 128);  // (8, 128)
    const dim3 gHID(HIDD  / 128, MROWS / 128);  // (32, 128)

    for (int i = 0; i < DEPTH; i++) {
        const __half* Wqkt_i = Wqkt + (size_t)i * 512 * DIMD;
        const __half* Wpt_i  = Wpt  + (size_t)i * ADIMD * ADIMD;
        const __half* Wft_i  = Wft  + (size_t)i * DIMD * ADIMD;
        const __half* W1t_i  = W1t  + (size_t)i * HIDD * DIMD;
        const __half* W2t_i  = W2t  + (size_t)i * DIMD * HIDD;

        // layer 0 reads x_in; residual buffer x is first written by the Wf GEMM
        ln_kernel<<<MROWS / 8, 256>>>(i == 0 ? x_in : x,
                                      ln1_g + i * DIMD, ln1_b + i * DIMD, h);
        // qk = h @ [Wq|Wk] + [bq|bk]
        hgemm<0><<<gQK2, 128, SMEM_HGEMM>>>(512, DIMD, DIMD, 0,
                                            h, Wqkt_i, bqk + i * 512, nullptr, qk);
        rnq_gsum_kernel<<<MROWS / 64, 256>>>(qk, w_g + i * ADIMD, a, Gp);
        gsum2_kernel<<<NB, 256>>>(Gp, a, G);
        rnk_scale_kernel<<<MROWS / 8, 256>>>(qk, G);
        // att = (G*k) @ Wp + bp + q
        hgemm<3><<<gP, 128, SMEM_HGEMM>>>(ADIMD, ADIMD, 512, 512,
                                          qk + 256, Wpt_i, bp + i * ADIMD, qk, att);
        // x (+)= att @ Wf + bf   (layer 0: x = x_in + att@Wf + bf)
        if (i == 0)
            hgemm<4><<<gDIM, 128, SMEM_HGEMM>>>(DIMD, ADIMD, ADIMD, DIMD,
                                                att, Wft_i, bf + i * DIMD, x_in, x);
        else
            hgemm<1><<<gDIM, 128, SMEM_HGEMM>>>(DIMD, ADIMD, ADIMD, 0,
                                                att, Wft_i, bf + i * DIMD, nullptr, x);
        ln_kernel<<<MROWS / 8, 256>>>(x, ln2_g + i * DIMD, ln2_b + i * DIMD, h);
        // hid = gelu(h @ W1 + b1)
        hgemm<2><<<gHID, 128, SMEM_HGEMM>>>(HIDD, DIMD, DIMD, 0,
                                            h, W1t_i, b1 + i * HIDD, nullptr, hid);
        // x += hid @ W2 + b2
        hgemm<1><<<gDIM, 128, SMEM_HGEMM>>>(DIMD, HIDD, HIDD, 0,
                                            hid, W2t_i, b2 + i * DIMD, nullptr, x);
    }
}

// round 16
// speedup vs baseline: 1.1284x; 1.1284x over previous
#include <cuda_runtime.h>
#include <cuda_fp16.h>
#include <math.h>
#include <stdint.h>

#define DIMD  1024
#define ADIMD 256
#define HIDD  4096
#define NTOK  4096
#define NB    4
#define MROWS (NB * NTOK)        // 16384
#define DEPTH 4
#define SCALE_A 0.25f

// ---------------- scratch (device globals) ----------------
__device__ __half g_h   [(size_t)MROWS * DIMD];
__device__ __half g_qk  [(size_t)MROWS * 512];      // q = cols [0,256), k = [256,512)
__device__ __half g_att [(size_t)MROWS * ADIMD];
__device__ __half g_hid [(size_t)MROWS * HIDD];
__device__ float  g_a   [MROWS];
__device__ float  g_G   [NB * ADIMD];
__device__ float  g_Gp  [256 * ADIMD];
__device__ float  g_bqk [DEPTH * 512];
__device__ __half g_Wqkt[(size_t)DEPTH * 512 * DIMD];   // [Wq|Wk] transposed
__device__ __half g_Wpt [(size_t)DEPTH * ADIMD * ADIMD];
__device__ __half g_Wft [(size_t)DEPTH * DIMD * ADIMD];
__device__ __half g_W1t [(size_t)DEPTH * HIDD * DIMD];
__device__ __half g_W2t [(size_t)DEPTH * DIMD * HIDD];

// ---------------- helpers ----------------
__device__ __forceinline__ float warpSum(float v) {
#pragma unroll
    for (int o = 16; o > 0; o >>= 1) v += __shfl_xor_sync(0xFFFFFFFFu, v, o);
    return v;
}
__device__ __forceinline__ uint32_t smem_u32(const void* p) {
    uint32_t a;
    asm("{ .reg .u64 t; cvta.to.shared.u64 t, %1; cvt.u32.u64 %0, t; }" : "=r"(a) : "l"(p));
    return a;
}
__device__ __forceinline__ void cp_async16(uint32_t saddr, const void* g) {
    asm volatile("cp.async.cg.shared.global [%0], [%1], 16;" :: "r"(saddr), "l"(g));
}
__device__ __forceinline__ void cp_commit() { asm volatile("cp.async.commit_group;"); }
template <int N> __device__ __forceinline__ void cp_wait() {
    asm volatile("cp.async.wait_group %0;" :: "n"(N));
}
__device__ __forceinline__ void ldsm4(uint32_t& r0, uint32_t& r1, uint32_t& r2, uint32_t& r3,
                                      uint32_t addr) {
    asm volatile("ldmatrix.sync.aligned.m8n8.x4.shared.b16 {%0,%1,%2,%3}, [%4];"
                 : "=r"(r0), "=r"(r1), "=r"(r2), "=r"(r3) : "r"(addr));
}
__device__ __forceinline__ void mma_f16(float& c0, float& c1, float& c2, float& c3,
                                        uint32_t a0, uint32_t a1, uint32_t a2, uint32_t a3,
                                        uint32_t b0, uint32_t b1) {
    asm volatile(
        "mma.sync.aligned.m16n8k16.row.col.f32.f16.f16.f32 "
        "{%0,%1,%2,%3}, {%4,%5,%6,%7}, {%8,%9}, {%0,%1,%2,%3};"
        : "+f"(c0), "+f"(c1), "+f"(c2), "+f"(c3)
        : "r"(a0), "r"(a1), "r"(a2), "r"(a3), "r"(b0), "r"(b1));
}

// == fp16 GEMM: CTA 128x128x32, 4 warps (2x2) of 64x64, 5 stages, dbl frags ==
#define A_BYTES     10240                 // 128 rows x 40 halfs (80B)
#define STAGE_BYTES 20480                 // A + B
#define NSTAGE      5
#define SMEM_HGEMM  (NSTAGE * STAGE_BYTES)  // 102400

// EPI: 0 = half(AB+bias) | 1 = Cf32 += AB+bias | 2 = half(gelu(AB+bias))
//      3 = half(AB+bias+Dhalf) | 4 = Cf32 = AB+bias+Dfloat
template <int EPI>
__global__ __launch_bounds__(128, 2)
void hgemm(int N, int K, int lda, int ldd,
           const __half* __restrict__ A,
           const __half* __restrict__ Bt,
           const float* __restrict__ bias,
           const void* __restrict__ Dadd,
           void* __restrict__ Cv) {
    extern __shared__ char smraw[];
    const uint32_t sbase = smem_u32(smraw);

    const int bx = blockIdx.x, by = blockIdx.y;
    const int tid = threadIdx.x;
    const int lane = tid & 31;
    const int warp = tid >> 5;           // 0..3
    const int warpM = warp & 1;          // 2 warps over M (64 rows each)
    const int warpN = warp >> 1;         // 2 warps over N (64 cols each)
    const int tg  = lane & 3;

    const __half* Ab = A  + (size_t)by * 128 * lda;
    const __half* Bb = Bt + (size_t)bx * 128 * K;

    const uint32_t a_lane = (uint32_t)((warpM * 64 + (lane & 15)) * 80 + (lane >> 4) * 16);
    const uint32_t b_lane = (uint32_t)(A_BYTES +
        (warpN * 64 + (lane & 7) + 8 * (lane >> 4)) * 80 + ((lane >> 3) & 1) * 16);

    float acc[4][8][4];
#pragma unroll
    for (int mi = 0; mi < 4; mi++)
#pragma unroll
        for (int ni = 0; ni < 8; ni++)
#pragma unroll
            for (int r = 0; r < 4; r++) acc[mi][ni][r] = 0.f;

    // double-buffered fragments
    uint32_t aF[2][4][4];     // [buf][mi][reg]
    uint32_t bF[2][8][2];     // [buf][ni][reg]

    const int T = K / 32;

    // A: 512 16B-chunks, B: 512 — 4 + 4 per thread (128 threads)
#define LOAD_TILE(t_, s_) do {                                                    \
        uint32_t _sa = sbase + (s_) * STAGE_BYTES;                                \
        uint32_t _sb = _sa + A_BYTES;                                             \
        const __half* _ga = Ab + (size_t)(t_) * 32;                              \
        const __half* _gb = Bb + (size_t)(t_) * 32;                              \
        _Pragma("unroll")                                                         \
        for (int _i = 0; _i < 4; _i++) {                                          \
            int _id = tid + _i * 128;                                             \
            int _r = _id >> 2, _c = _id & 3;                                      \
            cp_async16(_sa + _r * 80 + _c * 16, _ga + (size_t)_r * lda + _c * 8); \
            cp_async16(_sb + _r * 80 + _c * 16, _gb + (size_t)_r * K + _c * 8);   \
        }                                                                         \
        cp_commit();                                                              \
    } while (0)

#define LDSM_FRAGS(bufi, st_, ks_) do {                                           \
        uint32_t _a0 = (st_) + a_lane + (ks_) * 32;                               \
        _Pragma("unroll")                                                         \
        for (int _mi = 0; _mi < 4; _mi++)                                         \
            ldsm4(aF[bufi][_mi][0], aF[bufi][_mi][1],                             \
                  aF[bufi][_mi][2], aF[bufi][_mi][3], _a0 + _mi * 1280);          \
        uint32_t _b0 = (st_) + b_lane + (ks_) * 32;                               \
        _Pragma("unroll")                                                         \
        for (int _p = 0; _p < 4; _p++)                                            \
            ldsm4(bF[bufi][2*_p][0], bF[bufi][2*_p][1],                           \
                  bF[bufi][2*_p+1][0], bF[bufi][2*_p+1][1], _b0 + _p * 1280);     \
    } while (0)

#define DO_MMA(bufi) do {                                                         \
        _Pragma("unroll")                                                         \
        for (int mi = 0; mi < 4; mi++)                                            \
            _Pragma("unroll")                                                     \
            for (int ni = 0; ni < 8; ni++)                                        \
                mma_f16(acc[mi][ni][0], acc[mi][ni][1],                           \
                        acc[mi][ni][2], acc[mi][ni][3],                           \
                        aF[bufi][mi][0], aF[bufi][mi][1],                         \
                        aF[bufi][mi][2], aF[bufi][mi][3],                         \
                        bF[bufi][ni][0], bF[bufi][ni][1]);                        \
    } while (0)

    // prologue: 4 tiles in flight, frag buf0 = (tile0, ks0)
    LOAD_TILE(0, 0);
    if (T > 1) LOAD_TILE(1, 1); else cp_commit();
    if (T > 2) LOAD_TILE(2, 2); else cp_commit();
    if (T > 3) LOAD_TILE(3, 3); else cp_commit();
    cp_wait<3>();
    __syncthreads();
    LDSM_FRAGS(0, sbase, 0);

    int sc = 0;                 // slot of tile t
    for (int t = 0; t < T; t++) {
        const uint32_t st = sbase + sc * STAGE_BYTES;
        // prefetch (t, ks1), compute (t, ks0)
        LDSM_FRAGS(1, st, 1);
        DO_MMA(0);
        // issue tile t+4, advance to tile t+1, prefetch (t+1, ks0)
        if (t + 4 < T) LOAD_TILE(t + 4, (t + 4) % NSTAGE);
        else cp_commit();
        if (t + 1 < T) {
            cp_wait<3>();
            __syncthreads();
            int sn = (sc + 1 == NSTAGE) ? 0 : sc + 1;
            LDSM_FRAGS(0, sbase + sn * STAGE_BYTES, 0);
            sc = sn;
        }
        DO_MMA(1);
    }

    // epilogue
    const int grp8 = lane >> 2;
#pragma unroll
    for (int mi = 0; mi < 4; mi++) {
#pragma unroll
        for (int ni = 0; ni < 8; ni++) {
            int col = bx * 128 + warpN * 64 + ni * 8 + 2 * tg;
            int row0 = by * 128 + warpM * 64 + mi * 16 + grp8;
            float bv0 = bias[col], bv1 = bias[col + 1];
#pragma unroll
            for (int hh = 0; hh < 2; hh++) {
                int row = row0 + hh * 8;
                float v0 = acc[mi][ni][hh * 2 + 0] + bv0;
                float v1 = acc[mi][ni][hh * 2 + 1] + bv1;
                if (EPI == 1) {
                    float* Cp = (float*)Cv + (size_t)row * N + col;
                    float2 old = *(const float2*)Cp;
                    *(float2*)Cp = make_float2(v0 + old.x, v1 + old.y);
                } else if (EPI == 4) {
                    const float2 dv = *(const float2*)((const float*)Dadd +
                                                       (size_t)row * ldd + col);
                    float* Cp = (float*)Cv + (size_t)row * N + col;
                    *(float2*)Cp = make_float2(v0 + dv.x, v1 + dv.y);
                } else {
                    __half* Cp = (__half*)Cv + (size_t)row * N + col;
                    if (EPI == 2) {
                        v0 = 0.5f * v0 * (1.0f + erff(v0 * 0.70710678118654752f));
                        v1 = 0.5f * v1 * (1.0f + erff(v1 * 0.70710678118654752f));
                    }
                    if (EPI == 3) {
                        float2 dv = __half22float2(
                            *(const __half2*)((const __half*)Dadd +
                                              (size_t)row * ldd + col));
                        v0 += dv.x; v1 += dv.y;
                    }
                    *(__half2*)Cp = __floats2half2_rn(v0, v1);
                }
            }
        }
    }
}

// -------- single-launch transpose of ALL weights ---------------------------
#define TRANS_BLOCKS 36096
__global__ void transpose_all(const float* __restrict__ Wq, const float* __restrict__ Wk,
                              const float* __restrict__ Wp, const float* __restrict__ Wf,
                              const float* __restrict__ W1, const float* __restrict__ W2,
                              __half* __restrict__ Wqkt,
                              __half* __restrict__ Wpt, __half* __restrict__ Wft,
                              __half* __restrict__ W1t, __half* __restrict__ W2t) {
    int id = blockIdx.x;
    const float* W; __half* Wt; int K, N, base, orow;
    size_t ostride;
    if      (id < 1024)  { W = Wq; Wt = Wqkt; K = DIMD;  N = ADIMD; base = 0;
                           ostride = (size_t)512 * DIMD; orow = 0; }
    else if (id < 2048)  { W = Wk; Wt = Wqkt; K = DIMD;  N = ADIMD; base = 1024;
                           ostride = (size_t)512 * DIMD; orow = 256; }
    else if (id < 2304)  { W = Wp; Wt = Wpt;  K = ADIMD; N = ADIMD; base = 2048;
                           ostride = (size_t)K * N; orow = 0; }
    else if (id < 3328)  { W = Wf; Wt = Wft;  K = ADIMD; N = DIMD;  base = 2304;
                           ostride = (size_t)K * N; orow = 0; }
    else if (id < 19712) { W = W1; Wt = W1t;  K = DIMD;  N = HIDD;  base = 3328;
                           ostride = (size_t)K * N; orow = 0; }
    else                 { W = W2; Wt = W2t;  K = HIDD;  N = DIMD;  base = 19712;
                           ostride = (size_t)K * N; orow = 0; }
    int lid = id - base;
    int ntN = N >> 5;
    int tpl = (K >> 5) * ntN;
    int layer = lid / tpl;
    int rem   = lid % tpl;
    int n0 = (rem % ntN) * 32, k0 = (rem / ntN) * 32;
    size_t ioff = (size_t)layer * K * N;
    size_t ooff = (size_t)layer * ostride;

    __shared__ float t[32][33];
    int tx = threadIdx.x, ty = threadIdx.y;   // 32 x 8
#pragma unroll
    for (int i = 0; i < 4; i++)
        t[ty + 8 * i][tx] = W[ioff + (size_t)(k0 + ty + 8 * i) * N + n0 + tx];
    __syncthreads();
#pragma unroll
    for (int i = 0; i < 4; i++)
        Wt[ooff + (size_t)(orow + n0 + ty + 8 * i) * K + k0 + tx] =
            __float2half(t[tx][ty + 8 * i]);
}

// -------- pack [bq|bk] per layer -------------------------------------------
__global__ void pack_bias(const float* __restrict__ bq, const float* __restrict__ bk,
                          float* __restrict__ bqk) {
    int l = blockIdx.x, j = threadIdx.x;        // 512 threads
    bqk[l * 512 + j] = (j < 256) ? bq[l * 256 + j] : bk[l * 256 + j - 256];
}

// ---------------- LayerNorm: one warp per row ------------------------------
__global__ void ln_kernel(const float* __restrict__ x,
                          const float* __restrict__ g,
                          const float* __restrict__ b,
                          __half* __restrict__ out) {
    int row  = blockIdx.x * 8 + (threadIdx.x >> 5);
    int lane = threadIdx.x & 31;
    const float4* xr = (const float4*)(x + (size_t)row * DIMD);
    float4 v[8];
    float s = 0.f, s2 = 0.f;
#pragma unroll
    for (int j = 0; j < 8; j++) {
        v[j] = xr[lane + j * 32];
        s  += v[j].x + v[j].y + v[j].z + v[j].w;
        s2 += v[j].x*v[j].x + v[j].y*v[j].y + v[j].z*v[j].z + v[j].w*v[j].w;
    }
    s = warpSum(s); s2 = warpSum(s2);
    float mu  = s * (1.f / DIMD);
    float var = s2 * (1.f / DIMD) - mu * mu;
    float rs  = rsqrtf(var + 1e-6f);
    const float4* g4 = (const float4*)g;
    const float4* b4 = (const float4*)b;
    uint2* o = (uint2*)(out + (size_t)row * DIMD);
#pragma unroll
    for (int j = 0; j < 8; j++) {
        int c4 = lane + j * 32;
        float4 gg = g4[c4], bb = b4[c4];
        float o0 = (v[j].x - mu) * rs * gg.x + bb.x;
        float o1 = (v[j].y - mu) * rs * gg.y + bb.y;
        float o2 = (v[j].z - mu) * rs * gg.z + bb.z;
        float o3 = (v[j].w - mu) * rs * gg.w + bb.w;
        __half2 h0 = __floats2half2_rn(o0, o1);
        __half2 h1 = __floats2half2_rn(o2, o3);
        uint2 u;
        u.x = *(uint32_t*)&h0; u.y = *(uint32_t*)&h1;
        o[c4] = u;
    }
}

// ---- fused q pipeline: l2norm rows + a=SCALE*dot(qn,wg) + Gp partial -----
__global__ void rnq_gsum_kernel(__half* __restrict__ qk,
                                const float* __restrict__ wg,
                                float* __restrict__ a_out,
                                float* __restrict__ Gp) {
    __shared__ float a_sh[64];
    const int warp = threadIdx.x >> 5, lane = threadIdx.x & 31;
    const int row0 = blockIdx.x * 64;
    const float4* w4 = (const float4*)wg;
    const float4 w0 = w4[lane * 2], w1 = w4[lane * 2 + 1];

#pragma unroll 2
    for (int i = 0; i < 8; i++) {
        int r = warp * 8 + i;
        int row = row0 + r;
        float4* rp = (float4*)(qk + (size_t)row * 512);
        float4 v = rp[lane];
        __half2* h2 = (__half2*)&v;
        float2 f[4];
        float s = 0.f;
#pragma unroll
        for (int j = 0; j < 4; j++) {
            f[j] = __half22float2(h2[j]);
            s += f[j].x * f[j].x + f[j].y * f[j].y;
        }
        s = warpSum(s);
        float inv = 1.0f / fmaxf(sqrtf(s), 1e-12f);
#pragma unroll
        for (int j = 0; j < 4; j++) {
            f[j].x *= inv; f[j].y *= inv;
            h2[j] = __floats2half2_rn(f[j].x, f[j].y);
        }
        float d = f[0].x * w0.x + f[0].y * w0.y + f[1].x * w0.z + f[1].y * w0.w
                + f[2].x * w1.x + f[2].y * w1.y + f[3].x * w1.z + f[3].y * w1.w;
        d = warpSum(d);
        rp[lane] = v;
        if (lane == 0) {
            float av = d * SCALE_A;
            a_sh[r] = av;
            a_out[row] = av;
        }
    }
    __syncthreads();

    int c = threadIdx.x;
    const __half* qb = qk + (size_t)row0 * 512;
    float s = 0.f;
#pragma unroll 4
    for (int n = 0; n < 64; n++)
        s += a_sh[n] * __half2float(qb[(size_t)n * 512 + c]);
    Gp[(size_t)blockIdx.x * ADIMD + c] = s;
}

// ---- gsum2 with fused a-norm ----------------------------------------------
__global__ void gsum2_kernel(const float* __restrict__ Gp,
                             const float* __restrict__ a,
                             float* __restrict__ G) {
    int b = blockIdx.x;
    int c = threadIdx.x;
    float s = 0.f;
    for (int n = c; n < NTOK; n += 256) {
        float v = a[b * NTOK + n];
        s += v * v;
    }
    __shared__ float sh[8];
    s = warpSum(s);
    int w = c >> 5, l = c & 31;
    if (l == 0) sh[w] = s;
    __syncthreads();
    __shared__ float rn_sh;
    if (w == 0) {
        float v = (l < 8) ? sh[l] : 0.f;
        v = warpSum(v);
        if (l == 0) rn_sh = 1.0f / fmaxf(sqrtf(v), 1e-12f);
    }
    __syncthreads();
    float g = 0.f;
#pragma unroll
    for (int ch = 0; ch < 64; ch++)
        g += Gp[((size_t)b * 64 + ch) * ADIMD + c];
    G[b * ADIMD + c] = g * rn_sh;
}

// ---- k: l2norm + G scaling fused ------------------------------------------
__global__ void rnk_scale_kernel(__half* __restrict__ qk, const float* __restrict__ G) {
    int row  = blockIdx.x * 8 + (threadIdx.x >> 5);
    int lane = threadIdx.x & 31;
    int b = row >> 12;
    float4* r = (float4*)(qk + (size_t)row * 512 + 256);
    float4 v = r[lane];
    __half2* h2 = (__half2*)&v;
    float2 f[4];
    float s = 0.f;
#pragma unroll
    for (int i = 0; i < 4; i++) {
        f[i] = __half22float2(h2[i]);
        s += f[i].x * f[i].x + f[i].y * f[i].y;
    }
    s = warpSum(s);
    float inv = 1.0f / fmaxf(sqrtf(s), 1e-12f);
    const float4* G4 = (const float4*)(G + b * ADIMD);
    float4 g0 = G4[lane * 2], g1 = G4[lane * 2 + 1];
    h2[0] = __floats2half2_rn(f[0].x * inv * g0.x, f[0].y * inv * g0.y);
    h2[1] = __floats2half2_rn(f[1].x * inv * g0.z, f[1].y * inv * g0.w);
    h2[2] = __floats2half2_rn(f[2].x * inv * g1.x, f[2].y * inv * g1.y);
    h2[3] = __floats2half2_rn(f[3].x * inv * g1.z, f[3].y * inv * g1.w);
    r[lane] = v;
}

// ---------------- host orchestration --------------------------------------
extern "C" void kernel_launch(void* const* d_in, const int* in_sizes, int n_in,
                              void* d_out, int out_size) {
    const float* x_in  = (const float*)d_in[0];
    const float* ln1_g = (const float*)d_in[1];
    const float* ln1_b = (const float*)d_in[2];
    const float* Wq    = (const float*)d_in[3];
    const float* bq    = (const float*)d_in[4];
    const float* Wk    = (const float*)d_in[5];
    const float* bk    = (const float*)d_in[6];
    const float* w_g   = (const float*)d_in[7];
    const float* Wp    = (const float*)d_in[8];
    const float* bp    = (const float*)d_in[9];
    const float* Wf    = (const float*)d_in[10];
    const float* bf    = (const float*)d_in[11];
    const float* ln2_g = (const float*)d_in[12];
    const float* ln2_b = (const float*)d_in[13];
    const float* W1    = (const float*)d_in[14];
    const float* b1    = (const float*)d_in[15];
    const float* W2    = (const float*)d_in[16];
    const float* b2    = (const float*)d_in[17];

    float* x = (float*)d_out;

    void* p;
    cudaGetSymbolAddress(&p, g_h);    __half* h    = (__half*)p;
    cudaGetSymbolAddress(&p, g_qk);   __half* qk   = (__half*)p;
    cudaGetSymbolAddress(&p, g_att);  __half* att  = (__half*)p;
    cudaGetSymbolAddress(&p, g_hid);  __half* hid  = (__half*)p;
    cudaGetSymbolAddress(&p, g_a);    float* a     = (float*)p;
    cudaGetSymbolAddress(&p, g_G);    float* G     = (float*)p;
    cudaGetSymbolAddress(&p, g_Gp);   float* Gp    = (float*)p;
    cudaGetSymbolAddress(&p, g_bqk);  float* bqk   = (float*)p;
    cudaGetSymbolAddress(&p, g_Wqkt); __half* Wqkt = (__half*)p;
    cudaGetSymbolAddress(&p, g_Wpt);  __half* Wpt  = (__half*)p;
    cudaGetSymbolAddress(&p, g_Wft);  __half* Wft  = (__half*)p;
    cudaGetSymbolAddress(&p, g_W1t);  __half* W1t  = (__half*)p;
    cudaGetSymbolAddress(&p, g_W2t);  __half* W2t  = (__half*)p;

    cudaFuncSetAttribute(hgemm<0>, cudaFuncAttributeMaxDynamicSharedMemorySize, SMEM_HGEMM);
    cudaFuncSetAttribute(hgemm<1>, cudaFuncAttributeMaxDynamicSharedMemorySize, SMEM_HGEMM);
    cudaFuncSetAttribute(hgemm<2>, cudaFuncAttributeMaxDynamicSharedMemorySize, SMEM_HGEMM);
    cudaFuncSetAttribute(hgemm<3>, cudaFuncAttributeMaxDynamicSharedMemorySize, SMEM_HGEMM);
    cudaFuncSetAttribute(hgemm<4>, cudaFuncAttributeMaxDynamicSharedMemorySize, SMEM_HGEMM);

    transpose_all<<<TRANS_BLOCKS, dim3(32, 8)>>>(Wq, Wk, Wp, Wf, W1, W2,
                                                 Wqkt, Wpt, Wft, W1t, W2t);
    pack_bias<<<DEPTH, 512>>>(bq, bk, bqk);

    const dim3 gQK2(512  / 128, MROWS / 128);   // (4, 128)
    const dim3 gP  (ADIMD / 128, MROWS / 128);  // (2, 128)
    const dim3 gDIM(DIMD  / 128, MROWS / 128);  // (8, 128)
    const dim3 gHID(HIDD  / 128, MROWS / 128);  // (32, 128)

    for (int i = 0; i < DEPTH; i++) {
        const __half* Wqkt_i = Wqkt + (size_t)i * 512 * DIMD;
        const __half* Wpt_i  = Wpt  + (size_t)i * ADIMD * ADIMD;
        const __half* Wft_i  = Wft  + (size_t)i * DIMD * ADIMD;
        const __half* W1t_i  = W1t  + (size_t)i * HIDD * DIMD;
        const __half* W2t_i  = W2t  + (size_t)i * DIMD * HIDD;

        // layer 0 reads x_in; residual buffer x is first written by the Wf GEMM
        ln_kernel<<<MROWS / 8, 256>>>(i == 0 ? x_in : x,
                                      ln1_g + i * DIMD, ln1_b + i * DIMD, h);
        // qk = h @ [Wq|Wk] + [bq|bk]
        hgemm<0><<<gQK2, 128, SMEM_HGEMM>>>(512, DIMD, DIMD, 0,
                                            h, Wqkt_i, bqk + i * 512, nullptr, qk);
        rnq_gsum_kernel<<<MROWS / 64, 256>>>(qk, w_g + i * ADIMD, a, Gp);
        gsum2_kernel<<<NB, 256>>>(Gp, a, G);
        rnk_scale_kernel<<<MROWS / 8, 256>>>(qk, G);
        // att = (G*k) @ Wp + bp + q
        hgemm<3><<<gP, 128, SMEM_HGEMM>>>(ADIMD, ADIMD, 512, 512,
                                          qk + 256, Wpt_i, bp + i * ADIMD, qk, att);
        // x (+)= att @ Wf + bf   (layer 0: x = x_in + att@Wf + bf)
        if (i == 0)
            hgemm<4><<<gDIM, 128, SMEM_HGEMM>>>(DIMD, ADIMD, ADIMD, DIMD,
                                                att, Wft_i, bf + i * DIMD, x_in, x);
        else
            hgemm<1><<<gDIM, 128, SMEM_HGEMM>>>(DIMD, ADIMD, ADIMD, 0,
                                                att, Wft_i, bf + i * DIMD, nullptr, x);
        ln_kernel<<<MROWS / 8, 256>>>(x, ln2_g + i * DIMD, ln2_b + i * DIMD, h);
        // hid = gelu(h @ W1 + b1)
        hgemm<2><<<gHID, 128, SMEM_HGEMM>>>(HIDD, DIMD, DIMD, 0,
                                            h, W1t_i, b1 + i * HIDD, nullptr, hid);
        // x += hid @ W2 + b2
        hgemm<1><<<gDIM, 128, SMEM_HGEMM>>>(DIMD, HIDD, HIDD, 0,
                                            hid, W2t_i, b2 + i * DIMD, nullptr, x);
    }
}

// round 17
// speedup vs baseline: 1.1534x; 1.0222x over previous
#include <cuda_runtime.h>
#include <cuda_fp16.h>
#include <math.h>
#include <stdint.h>

#define DIMD  1024
#define ADIMD 256
#define HIDD  4096
#define NTOK  4096
#define NB    4
#define MROWS (NB * NTOK)        // 16384
#define DEPTH 4
#define SCALE_A 0.25f

// ---------------- scratch (device globals) ----------------
__device__ __half g_h   [(size_t)MROWS * DIMD];
__device__ __half g_qk  [(size_t)MROWS * 512];      // q = cols [0,256), k = [256,512)
__device__ __half g_att [(size_t)MROWS * ADIMD];
__device__ __half g_hid [(size_t)MROWS * HIDD];
__device__ float  g_a   [MROWS];
__device__ float  g_G   [NB * ADIMD];
__device__ float  g_Gp  [256 * ADIMD];
__device__ float  g_bqk [DEPTH * 512];
__device__ __half g_Wqkt[(size_t)DEPTH * 512 * DIMD];   // [Wq|Wk] transposed
__device__ __half g_Wpt [(size_t)DEPTH * ADIMD * ADIMD];
__device__ __half g_Wft [(size_t)DEPTH * DIMD * ADIMD];
__device__ __half g_W1t [(size_t)DEPTH * HIDD * DIMD];
__device__ __half g_W2t [(size_t)DEPTH * DIMD * HIDD];

// ---------------- helpers ----------------
__device__ __forceinline__ float warpSum(float v) {
#pragma unroll
    for (int o = 16; o > 0; o >>= 1) v += __shfl_xor_sync(0xFFFFFFFFu, v, o);
    return v;
}
__device__ __forceinline__ uint32_t smem_u32(const void* p) {
    uint32_t a;
    asm("{ .reg .u64 t; cvta.to.shared.u64 t, %1; cvt.u32.u64 %0, t; }" : "=r"(a) : "l"(p));
    return a;
}
__device__ __forceinline__ void cp_async16(uint32_t saddr, const void* g) {
    asm volatile("cp.async.cg.shared.global [%0], [%1], 16;" :: "r"(saddr), "l"(g));
}
__device__ __forceinline__ void cp_commit() { asm volatile("cp.async.commit_group;"); }
template <int N> __device__ __forceinline__ void cp_wait() {
    asm volatile("cp.async.wait_group %0;" :: "n"(N));
}
__device__ __forceinline__ void ldsm4(uint32_t& r0, uint32_t& r1, uint32_t& r2, uint32_t& r3,
                                      uint32_t addr) {
    asm volatile("ldmatrix.sync.aligned.m8n8.x4.shared.b16 {%0,%1,%2,%3}, [%4];"
                 : "=r"(r0), "=r"(r1), "=r"(r2), "=r"(r3) : "r"(addr));
}
__device__ __forceinline__ void mma_f16(float& c0, float& c1, float& c2, float& c3,
                                        uint32_t a0, uint32_t a1, uint32_t a2, uint32_t a3,
                                        uint32_t b0, uint32_t b1) {
    asm volatile(
        "mma.sync.aligned.m16n8k16.row.col.f32.f16.f16.f32 "
        "{%0,%1,%2,%3}, {%4,%5,%6,%7}, {%8,%9}, {%0,%1,%2,%3};"
        : "+f"(c0), "+f"(c1), "+f"(c2), "+f"(c3)
        : "r"(a0), "r"(a1), "r"(a2), "r"(a3), "r"(b0), "r"(b1));
}

// == fp16 GEMM: CTA 128x128, 4 warps (2x2) of 64x64, BK=64 stages x3 ========
// Stage layout: A 128 rows x 72 halfs (144B row), B same. Stage = 36864B.
#define A_ST_BYTES  18432
#define STAGE_BYTES 36864
#define NSTAGE      3
#define SMEM_HGEMM  (NSTAGE * STAGE_BYTES)   // 110592; x2 CTAs = 221184 < 228KB

// EPI: 0 = half(AB+bias) | 1 = Cf32 += AB+bias | 2 = half(gelu(AB+bias))
//      3 = half(AB+bias+Dhalf) | 4 = Cf32 = AB+bias+Dfloat
template <int EPI>
__global__ __launch_bounds__(128, 2)
void hgemm(int N, int K, int lda, int ldd,
           const __half* __restrict__ A,
           const __half* __restrict__ Bt,
           const float* __restrict__ bias,
           const void* __restrict__ Dadd,
           void* __restrict__ Cv) {
    extern __shared__ char smraw[];
    const uint32_t sbase = smem_u32(smraw);

    const int bx = blockIdx.x, by = blockIdx.y;
    const int tid = threadIdx.x;
    const int lane = tid & 31;
    const int warp = tid >> 5;           // 0..3
    const int warpM = warp & 1;          // 2 warps over M (64 rows each)
    const int warpN = warp >> 1;         // 2 warps over N (64 cols each)
    const int tg  = lane & 3;

    const __half* Ab = A  + (size_t)by * 128 * lda;
    const __half* Bb = Bt + (size_t)bx * 128 * K;

    // ldmatrix lane bases (144B row stride)
    const uint32_t a_lane = (uint32_t)((warpM * 64 + (lane & 15)) * 144 + (lane >> 4) * 16);
    const uint32_t b_lane = (uint32_t)(A_ST_BYTES +
        (warpN * 64 + (lane & 7) + 8 * (lane >> 4)) * 144 + ((lane >> 3) & 1) * 16);

    float acc[4][8][4];
#pragma unroll
    for (int mi = 0; mi < 4; mi++)
#pragma unroll
        for (int ni = 0; ni < 8; ni++)
#pragma unroll
            for (int r = 0; r < 4; r++) acc[mi][ni][r] = 0.f;

    // double-buffered fragments
    uint32_t aF[2][4][4];     // [buf][mi][reg]
    uint32_t bF[2][8][2];     // [buf][ni][reg]

    const int S = K / 64;     // BK=64 stages (K >= 256 -> S >= 4)

    // per stage: A 128x64 halfs = 1024 16B chunks; B same. 8+8 per thread.
#define LOAD_STAGE(t_, s_) do {                                                   \
        uint32_t _sa = sbase + (s_) * STAGE_BYTES;                                \
        uint32_t _sb = _sa + A_ST_BYTES;                                          \
        const __half* _ga = Ab + (size_t)(t_) * 64;                              \
        const __half* _gb = Bb + (size_t)(t_) * 64;                              \
        _Pragma("unroll")                                                         \
        for (int _i = 0; _i < 8; _i++) {                                          \
            int _id = tid + _i * 128;                                             \
            int _r = _id >> 3, _c = _id & 7;                                      \
            cp_async16(_sa + _r * 144 + _c * 16, _ga + (size_t)_r * lda + _c * 8); \
            cp_async16(_sb + _r * 144 + _c * 16, _gb + (size_t)_r * K + _c * 8);   \
        }                                                                         \
        cp_commit();                                                              \
    } while (0)

#define LDSM_FRAGS(bufi, st_, ks_) do {                                           \
        uint32_t _a0 = (st_) + a_lane + (ks_) * 32;                               \
        _Pragma("unroll")                                                         \
        for (int _mi = 0; _mi < 4; _mi++)                                         \
            ldsm4(aF[bufi][_mi][0], aF[bufi][_mi][1],                             \
                  aF[bufi][_mi][2], aF[bufi][_mi][3], _a0 + _mi * 2304);          \
        uint32_t _b0 = (st_) + b_lane + (ks_) * 32;                               \
        _Pragma("unroll")                                                         \
        for (int _p = 0; _p < 4; _p++)                                            \
            ldsm4(bF[bufi][2*_p][0], bF[bufi][2*_p][1],                           \
                  bF[bufi][2*_p+1][0], bF[bufi][2*_p+1][1], _b0 + _p * 2304);     \
    } while (0)

#define DO_MMA(bufi) do {                                                         \
        _Pragma("unroll")                                                         \
        for (int mi = 0; mi < 4; mi++)                                            \
            _Pragma("unroll")                                                     \
            for (int ni = 0; ni < 8; ni++)                                        \
                mma_f16(acc[mi][ni][0], acc[mi][ni][1],                           \
                        acc[mi][ni][2], acc[mi][ni][3],                           \
                        aF[bufi][mi][0], aF[bufi][mi][1],                         \
                        aF[bufi][mi][2], aF[bufi][mi][3],                         \
                        bF[bufi][ni][0], bF[bufi][ni][1]);                        \
    } while (0)

    // prologue: stages 0,1 in flight; stage 0 resident; frag buf0 = (0, ks0)
    LOAD_STAGE(0, 0);
    LOAD_STAGE(1, 1);
    cp_wait<1>();
    __syncthreads();
    LDSM_FRAGS(0, sbase, 0);

    for (int t = 0; t < S; t++) {
        // slot (t+2)%3 was fully read in iter t-1 (before its sync) -> reusable
        if (t + 2 < S) LOAD_STAGE(t + 2, (t + 2) % NSTAGE);
        else cp_commit();
        const uint32_t st = sbase + (t % NSTAGE) * STAGE_BYTES;
        LDSM_FRAGS(1, st, 1);  DO_MMA(0);
        LDSM_FRAGS(0, st, 2);  DO_MMA(1);
        LDSM_FRAGS(1, st, 3);  DO_MMA(0);
        if (t + 1 < S) {
            cp_wait<1>();            // stage t+1 resident (one newer group pending)
            __syncthreads();         // retire all reads of stage t
            LDSM_FRAGS(0, sbase + ((t + 1) % NSTAGE) * STAGE_BYTES, 0);
        }
        DO_MMA(1);
    }

    // epilogue
    const int grp8 = lane >> 2;
#pragma unroll
    for (int mi = 0; mi < 4; mi++) {
#pragma unroll
        for (int ni = 0; ni < 8; ni++) {
            int col = bx * 128 + warpN * 64 + ni * 8 + 2 * tg;
            int row0 = by * 128 + warpM * 64 + mi * 16 + grp8;
            float bv0 = bias[col], bv1 = bias[col + 1];
#pragma unroll
            for (int hh = 0; hh < 2; hh++) {
                int row = row0 + hh * 8;
                float v0 = acc[mi][ni][hh * 2 + 0] + bv0;
                float v1 = acc[mi][ni][hh * 2 + 1] + bv1;
                if (EPI == 1) {
                    float* Cp = (float*)Cv + (size_t)row * N + col;
                    float2 old = *(const float2*)Cp;
                    *(float2*)Cp = make_float2(v0 + old.x, v1 + old.y);
                } else if (EPI == 4) {
                    const float2 dv = *(const float2*)((const float*)Dadd +
                                                       (size_t)row * ldd + col);
                    float* Cp = (float*)Cv + (size_t)row * N + col;
                    *(float2*)Cp = make_float2(v0 + dv.x, v1 + dv.y);
                } else {
                    __half* Cp = (__half*)Cv + (size_t)row * N + col;
                    if (EPI == 2) {
                        v0 = 0.5f * v0 * (1.0f + erff(v0 * 0.70710678118654752f));
                        v1 = 0.5f * v1 * (1.0f + erff(v1 * 0.70710678118654752f));
                    }
                    if (EPI == 3) {
                        float2 dv = __half22float2(
                            *(const __half2*)((const __half*)Dadd +
                                              (size_t)row * ldd + col));
                        v0 += dv.x; v1 += dv.y;
                    }
                    *(__half2*)Cp = __floats2half2_rn(v0, v1);
                }
            }
        }
    }
}

// -------- single-launch transpose of ALL weights ---------------------------
#define TRANS_BLOCKS 36096
__global__ void transpose_all(const float* __restrict__ Wq, const float* __restrict__ Wk,
                              const float* __restrict__ Wp, const float* __restrict__ Wf,
                              const float* __restrict__ W1, const float* __restrict__ W2,
                              __half* __restrict__ Wqkt,
                              __half* __restrict__ Wpt, __half* __restrict__ Wft,
                              __half* __restrict__ W1t, __half* __restrict__ W2t) {
    int id = blockIdx.x;
    const float* W; __half* Wt; int K, N, base, orow;
    size_t ostride;
    if      (id < 1024)  { W = Wq; Wt = Wqkt; K = DIMD;  N = ADIMD; base = 0;
                           ostride = (size_t)512 * DIMD; orow = 0; }
    else if (id < 2048)  { W = Wk; Wt = Wqkt; K = DIMD;  N = ADIMD; base = 1024;
                           ostride = (size_t)512 * DIMD; orow = 256; }
    else if (id < 2304)  { W = Wp; Wt = Wpt;  K = ADIMD; N = ADIMD; base = 2048;
                           ostride = (size_t)K * N; orow = 0; }
    else if (id < 3328)  { W = Wf; Wt = Wft;  K = ADIMD; N = DIMD;  base = 2304;
                           ostride = (size_t)K * N; orow = 0; }
    else if (id < 19712) { W = W1; Wt = W1t;  K = DIMD;  N = HIDD;  base = 3328;
                           ostride = (size_t)K * N; orow = 0; }
    else                 { W = W2; Wt = W2t;  K = HIDD;  N = DIMD;  base = 19712;
                           ostride = (size_t)K * N; orow = 0; }
    int lid = id - base;
    int ntN = N >> 5;
    int tpl = (K >> 5) * ntN;
    int layer = lid / tpl;
    int rem   = lid % tpl;
    int n0 = (rem % ntN) * 32, k0 = (rem / ntN) * 32;
    size_t ioff = (size_t)layer * K * N;
    size_t ooff = (size_t)layer * ostride;

    __shared__ float t[32][33];
    int tx = threadIdx.x, ty = threadIdx.y;   // 32 x 8
#pragma unroll
    for (int i = 0; i < 4; i++)
        t[ty + 8 * i][tx] = W[ioff + (size_t)(k0 + ty + 8 * i) * N + n0 + tx];
    __syncthreads();
#pragma unroll
    for (int i = 0; i < 4; i++)
        Wt[ooff + (size_t)(orow + n0 + ty + 8 * i) * K + k0 + tx] =
            __float2half(t[tx][ty + 8 * i]);
}

// -------- pack [bq|bk] per layer -------------------------------------------
__global__ void pack_bias(const float* __restrict__ bq, const float* __restrict__ bk,
                          float* __restrict__ bqk) {
    int l = blockIdx.x, j = threadIdx.x;        // 512 threads
    bqk[l * 512 + j] = (j < 256) ? bq[l * 256 + j] : bk[l * 256 + j - 256];
}

// ---------------- LayerNorm: one warp per row ------------------------------
__global__ void ln_kernel(const float* __restrict__ x,
                          const float* __restrict__ g,
                          const float* __restrict__ b,
                          __half* __restrict__ out) {
    int row  = blockIdx.x * 8 + (threadIdx.x >> 5);
    int lane = threadIdx.x & 31;
    const float4* xr = (const float4*)(x + (size_t)row * DIMD);
    float4 v[8];
    float s = 0.f, s2 = 0.f;
#pragma unroll
    for (int j = 0; j < 8; j++) {
        v[j] = xr[lane + j * 32];
        s  += v[j].x + v[j].y + v[j].z + v[j].w;
        s2 += v[j].x*v[j].x + v[j].y*v[j].y + v[j].z*v[j].z + v[j].w*v[j].w;
    }
    s = warpSum(s); s2 = warpSum(s2);
    float mu  = s * (1.f / DIMD);
    float var = s2 * (1.f / DIMD) - mu * mu;
    float rs  = rsqrtf(var + 1e-6f);
    const float4* g4 = (const float4*)g;
    const float4* b4 = (const float4*)b;
    uint2* o = (uint2*)(out + (size_t)row * DIMD);
#pragma unroll
    for (int j = 0; j < 8; j++) {
        int c4 = lane + j * 32;
        float4 gg = g4[c4], bb = b4[c4];
        float o0 = (v[j].x - mu) * rs * gg.x + bb.x;
        float o1 = (v[j].y - mu) * rs * gg.y + bb.y;
        float o2 = (v[j].z - mu) * rs * gg.z + bb.z;
        float o3 = (v[j].w - mu) * rs * gg.w + bb.w;
        __half2 h0 = __floats2half2_rn(o0, o1);
        __half2 h1 = __floats2half2_rn(o2, o3);
        uint2 u;
        u.x = *(uint32_t*)&h0; u.y = *(uint32_t*)&h1;
        o[c4] = u;
    }
}

// ---- fused q pipeline: l2norm rows + a=SCALE*dot(qn,wg) + Gp partial -----
__global__ void rnq_gsum_kernel(__half* __restrict__ qk,
                                const float* __restrict__ wg,
                                float* __restrict__ a_out,
                                float* __restrict__ Gp) {
    __shared__ float a_sh[64];
    const int warp = threadIdx.x >> 5, lane = threadIdx.x & 31;
    const int row0 = blockIdx.x * 64;
    const float4* w4 = (const float4*)wg;
    const float4 w0 = w4[lane * 2], w1 = w4[lane * 2 + 1];

#pragma unroll 2
    for (int i = 0; i < 8; i++) {
        int r = warp * 8 + i;
        int row = row0 + r;
        float4* rp = (float4*)(qk + (size_t)row * 512);
        float4 v = rp[lane];
        __half2* h2 = (__half2*)&v;
        float2 f[4];
        float s = 0.f;
#pragma unroll
        for (int j = 0; j < 4; j++) {
            f[j] = __half22float2(h2[j]);
            s += f[j].x * f[j].x + f[j].y * f[j].y;
        }
        s = warpSum(s);
        float inv = 1.0f / fmaxf(sqrtf(s), 1e-12f);
#pragma unroll
        for (int j = 0; j < 4; j++) {
            f[j].x *= inv; f[j].y *= inv;
            h2[j] = __floats2half2_rn(f[j].x, f[j].y);
        }
        float d = f[0].x * w0.x + f[0].y * w0.y + f[1].x * w0.z + f[1].y * w0.w
                + f[2].x * w1.x + f[2].y * w1.y + f[3].x * w1.z + f[3].y * w1.w;
        d = warpSum(d);
        rp[lane] = v;
        if (lane == 0) {
            float av = d * SCALE_A;
            a_sh[r] = av;
            a_out[row] = av;
        }
    }
    __syncthreads();

    int c = threadIdx.x;
    const __half* qb = qk + (size_t)row0 * 512;
    float s = 0.f;
#pragma unroll 4
    for (int n = 0; n < 64; n++)
        s += a_sh[n] * __half2float(qb[(size_t)n * 512 + c]);
    Gp[(size_t)blockIdx.x * ADIMD + c] = s;
}

// ---- gsum2 with fused a-norm ----------------------------------------------
__global__ void gsum2_kernel(const float* __restrict__ Gp,
                             const float* __restrict__ a,
                             float* __restrict__ G) {
    int b = blockIdx.x;
    int c = threadIdx.x;
    float s = 0.f;
    for (int n = c; n < NTOK; n += 256) {
        float v = a[b * NTOK + n];
        s += v * v;
    }
    __shared__ float sh[8];
    s = warpSum(s);
    int w = c >> 5, l = c & 31;
    if (l == 0) sh[w] = s;
    __syncthreads();
    __shared__ float rn_sh;
    if (w == 0) {
        float v = (l < 8) ? sh[l] : 0.f;
        v = warpSum(v);
        if (l == 0) rn_sh = 1.0f / fmaxf(sqrtf(v), 1e-12f);
    }
    __syncthreads();
    float g = 0.f;
#pragma unroll
    for (int ch = 0; ch < 64; ch++)
        g += Gp[((size_t)b * 64 + ch) * ADIMD + c];
    G[b * ADIMD + c] = g * rn_sh;
}

// ---- k: l2norm + G scaling fused ------------------------------------------
__global__ void rnk_scale_kernel(__half* __restrict__ qk, const float* __restrict__ G) {
    int row  = blockIdx.x * 8 + (threadIdx.x >> 5);
    int lane = threadIdx.x & 31;
    int b = row >> 12;
    float4* r = (float4*)(qk + (size_t)row * 512 + 256);
    float4 v = r[lane];
    __half2* h2 = (__half2*)&v;
    float2 f[4];
    float s = 0.f;
#pragma unroll
    for (int i = 0; i < 4; i++) {
        f[i] = __half22float2(h2[i]);
        s += f[i].x * f[i].x + f[i].y * f[i].y;
    }
    s = warpSum(s);
    float inv = 1.0f / fmaxf(sqrtf(s), 1e-12f);
    const float4* G4 = (const float4*)(G + b * ADIMD);
    float4 g0 = G4[lane * 2], g1 = G4[lane * 2 + 1];
    h2[0] = __floats2half2_rn(f[0].x * inv * g0.x, f[0].y * inv * g0.y);
    h2[1] = __floats2half2_rn(f[1].x * inv * g0.z, f[1].y * inv * g0.w);
    h2[2] = __floats2half2_rn(f[2].x * inv * g1.x, f[2].y * inv * g1.y);
    h2[3] = __floats2half2_rn(f[3].x * inv * g1.z, f[3].y * inv * g1.w);
    r[lane] = v;
}

// ---------------- host orchestration --------------------------------------
extern "C" void kernel_launch(void* const* d_in, const int* in_sizes, int n_in,
                              void* d_out, int out_size) {
    const float* x_in  = (const float*)d_in[0];
    const float* ln1_g = (const float*)d_in[1];
    const float* ln1_b = (const float*)d_in[2];
    const float* Wq    = (const float*)d_in[3];
    const float* bq    = (const float*)d_in[4];
    const float* Wk    = (const float*)d_in[5];
    const float* bk    = (const float*)d_in[6];
    const float* w_g   = (const float*)d_in[7];
    const float* Wp    = (const float*)d_in[8];
    const float* bp    = (const float*)d_in[9];
    const float* Wf    = (const float*)d_in[10];
    const float* bf    = (const float*)d_in[11];
    const float* ln2_g = (const float*)d_in[12];
    const float* ln2_b = (const float*)d_in[13];
    const float* W1    = (const float*)d_in[14];
    const float* b1    = (const float*)d_in[15];
    const float* W2    = (const float*)d_in[16];
    const float* b2    = (const float*)d_in[17];

    float* x = (float*)d_out;

    void* p;
    cudaGetSymbolAddress(&p, g_h);    __half* h    = (__half*)p;
    cudaGetSymbolAddress(&p, g_qk);   __half* qk   = (__half*)p;
    cudaGetSymbolAddress(&p, g_att);  __half* att  = (__half*)p;
    cudaGetSymbolAddress(&p, g_hid);  __half* hid  = (__half*)p;
    cudaGetSymbolAddress(&p, g_a);    float* a     = (float*)p;
    cudaGetSymbolAddress(&p, g_G);    float* G     = (float*)p;
    cudaGetSymbolAddress(&p, g_Gp);   float* Gp    = (float*)p;
    cudaGetSymbolAddress(&p, g_bqk);  float* bqk   = (float*)p;
    cudaGetSymbolAddress(&p, g_Wqkt); __half* Wqkt = (__half*)p;
    cudaGetSymbolAddress(&p, g_Wpt);  __half* Wpt  = (__half*)p;
    cudaGetSymbolAddress(&p, g_Wft);  __half* Wft  = (__half*)p;
    cudaGetSymbolAddress(&p, g_W1t);  __half* W1t  = (__half*)p;
    cudaGetSymbolAddress(&p, g_W2t);  __half* W2t  = (__half*)p;

    cudaFuncSetAttribute(hgemm<0>, cudaFuncAttributeMaxDynamicSharedMemorySize, SMEM_HGEMM);
    cudaFuncSetAttribute(hgemm<1>, cudaFuncAttributeMaxDynamicSharedMemorySize, SMEM_HGEMM);
    cudaFuncSetAttribute(hgemm<2>, cudaFuncAttributeMaxDynamicSharedMemorySize, SMEM_HGEMM);
    cudaFuncSetAttribute(hgemm<3>, cudaFuncAttributeMaxDynamicSharedMemorySize, SMEM_HGEMM);
    cudaFuncSetAttribute(hgemm<4>, cudaFuncAttributeMaxDynamicSharedMemorySize, SMEM_HGEMM);

    transpose_all<<<TRANS_BLOCKS, dim3(32, 8)>>>(Wq, Wk, Wp, Wf, W1, W2,
                                                 Wqkt, Wpt, Wft, W1t, W2t);
    pack_bias<<<DEPTH, 512>>>(bq, bk, bqk);

    const dim3 gQK2(512  / 128, MROWS / 128);   // (4, 128)
    const dim3 gP  (ADIMD / 128, MROWS / 128);  // (2, 128)
    const dim3 gDIM(DIMD  / 128, MROWS / 128);  // (8, 128)
    const dim3 gHID(HIDD  / 128, MROWS / 128);  // (32, 128)

    for (int i = 0; i < DEPTH; i++) {
        const __half* Wqkt_i = Wqkt + (size_t)i * 512 * DIMD;
        const __half* Wpt_i  = Wpt  + (size_t)i * ADIMD * ADIMD;
        const __half* Wft_i  = Wft  + (size_t)i * DIMD * ADIMD;
        const __half* W1t_i  = W1t  + (size_t)i * HIDD * DIMD;
        const __half* W2t_i  = W2t  + (size_t)i * DIMD * HIDD;

        // layer 0 reads x_in; residual buffer x is first written by the Wf GEMM
        ln_kernel<<<MROWS / 8, 256>>>(i == 0 ? x_in : x,
                                      ln1_g + i * DIMD, ln1_b + i * DIMD, h);
        // qk = h @ [Wq|Wk] + [bq|bk]
        hgemm<0><<<gQK2, 128, SMEM_HGEMM>>>(512, DIMD, DIMD, 0,
                                            h, Wqkt_i, bqk + i * 512, nullptr, qk);
        rnq_gsum_kernel<<<MROWS / 64, 256>>>(qk, w_g + i * ADIMD, a, Gp);
        gsum2_kernel<<<NB, 256>>>(Gp, a, G);
        rnk_scale_kernel<<<MROWS / 8, 256>>>(qk, G);
        // att = (G*k) @ Wp + bp + q
        hgemm<3><<<gP, 128, SMEM_HGEMM>>>(ADIMD, ADIMD, 512, 512,
                                          qk + 256, Wpt_i, bp + i * ADIMD, qk, att);
        // x (+)= att @ Wf + bf   (layer 0: x = x_in + att@Wf + bf)
        if (i == 0)
            hgemm<4><<<gDIM, 128, SMEM_HGEMM>>>(DIMD, ADIMD, ADIMD, DIMD,
                                                att, Wft_i, bf + i * DIMD, x_in, x);
        else
            hgemm<1><<<gDIM, 128, SMEM_HGEMM>>>(DIMD, ADIMD, ADIMD, 0,
                                                att, Wft_i, bf + i * DIMD, nullptr, x);
        ln_kernel<<<MROWS / 8, 256>>>(x, ln2_g + i * DIMD, ln2_b + i * DIMD, h);
        // hid = gelu(h @ W1 + b1)
        hgemm<2><<<gHID, 128, SMEM_HGEMM>>>(HIDD, DIMD, DIMD, 0,
                                            h, W1t_i, b1 + i * HIDD, nullptr, hid);
        // x += hid @ W2 + b2
        hgemm<1><<<gDIM, 128, SMEM_HGEMM>>>(DIMD, HIDD, HIDD, 0,
                                            hid, W2t_i, b2 + i * DIMD, nullptr, x);
    }
}